// round 2
// baseline (speedup 1.0000x reference)
#include <cuda_runtime.h>
#include <math.h>

#define NCAP 64
#define DDIM 64
#define PAD  65
#define THREADS 128
#define EPS 1e-8f

// 4-warp block reduction helpers (all 128 threads must call; inactive pass neutral)
__device__ __forceinline__ float block_reduce_max(float val, float* scratch) {
    #pragma unroll
    for (int o = 16; o > 0; o >>= 1)
        val = fmaxf(val, __shfl_xor_sync(0xFFFFFFFFu, val, o));
    int warp = threadIdx.x >> 5;
    int lane = threadIdx.x & 31;
    if (lane == 0) scratch[warp] = val;
    __syncthreads();
    float r = fmaxf(fmaxf(scratch[0], scratch[1]), fmaxf(scratch[2], scratch[3]));
    __syncthreads();
    return r;
}

__device__ __forceinline__ float block_reduce_sum(float val, float* scratch) {
    #pragma unroll
    for (int o = 16; o > 0; o >>= 1)
        val += __shfl_xor_sync(0xFFFFFFFFu, val, o);
    int warp = threadIdx.x >> 5;
    int lane = threadIdx.x & 31;
    if (lane == 0) scratch[warp] = val;
    __syncthreads();
    float r = scratch[0] + scratch[1] + scratch[2] + scratch[3];
    __syncthreads();
    return r;
}

__global__ __launch_bounds__(THREADS)
void routing_kernel(const float* __restrict__ caps, float* __restrict__ out) {
    __shared__ float U[NCAP][PAD];     // 64x65 fp32, pad kills bank conflicts both ways
    __shared__ float red[4];
    __shared__ float cvec[NCAP];
    __shared__ float vvec[DDIM];

    const int tid = threadIdx.x;
    const int blk = blockIdx.x;

    // ---- Load 64x64 tile (16 KB) coalesced via float4: 1024 float4 / 128 thr = 8 each
    const float4* src = reinterpret_cast<const float4*>(caps + (size_t)blk * NCAP * DDIM);
    #pragma unroll
    for (int i = 0; i < 8; i++) {
        int idx = tid + i * THREADS;          // 0..1023 float4 index
        float4 v4 = src[idx];
        int r = idx >> 4;                     // 16 float4 per row
        int c = (idx & 15) << 2;
        U[r][c + 0] = v4.x;
        U[r][c + 1] = v4.y;
        U[r][c + 2] = v4.z;
        U[r][c + 3] = v4.w;
    }
    __syncthreads();

    const bool active = (tid < 64);
    float b_log = 0.0f;     // routing logit for capsule n = tid
    float v_d   = 0.0f;     // output dim d = tid

    #pragma unroll
    for (int it = 0; it < 3; it++) {
        // ---- softmax over N (axis=1): c_n = exp(b_n - max) / sum
        // it==0: b == 0 everywhere -> softmax is exactly uniform 1/64; skip reductions.
        if (it == 0) {
            if (active) cvec[tid] = 1.0f / 64.0f;
        } else {
            float m = block_reduce_max(active ? b_log : -INFINITY, red);
            float e = active ? __expf(b_log - m) : 0.0f;
            float Z = block_reduce_sum(e, red);
            if (active) cvec[tid] = e / Z;
        }
        __syncthreads();

        // ---- s[d] = sum_n c[n] * U[n][d]   (thread d reads column d, conflict-free)
        float s = 0.0f;
        if (active) {
            #pragma unroll
            for (int n = 0; n < NCAP; n++)
                s = fmaf(cvec[n], U[n][tid], s);
        }

        // ---- squash: v = (|s|^2 / (1+|s|^2)) * s / (|s| + eps)
        float ss = block_reduce_sum(active ? s * s : 0.0f, red);
        float nrm = sqrtf(ss);
        float scale = ss / (1.0f + ss) / (nrm + EPS);
        v_d = scale * s;
        if (active) vvec[tid] = v_d;
        __syncthreads();

        // ---- agreement: b_n += sum_d U[n][d] * v[d]  (thread n reads row n, stride 65 ≡ 1 mod 32)
        if (it < 2 && active) {
            float a = 0.0f;
            #pragma unroll
            for (int d = 0; d < DDIM; d++)
                a = fmaf(U[tid][d], vvec[d], a);
            b_log += a;
        }
        __syncthreads();
    }

    if (active)
        out[(size_t)blk * DDIM + tid] = v_d;
}

extern "C" void kernel_launch(void* const* d_in, const int* in_sizes, int n_in,
                              void* d_out, int out_size) {
    const float* caps = (const float*)d_in[0];
    float* out = (float*)d_out;
    int B = in_sizes[0] / (NCAP * DDIM);   // 16384
    routing_kernel<<<B, THREADS>>>(caps, out);
}

// round 6
// speedup vs baseline: 1.9058x; 1.9058x over previous
#include <cuda_runtime.h>
#include <math.h>

#define THREADS 128
#define NCAP 64
#define DDIM 64
#define EPS 1e-8f

// bit-reverse of low 4 bits (involution): maps lane <-> row within a warp's 16 rows
__device__ __forceinline__ int brev4(int x) {
    return ((x & 1) << 3) | ((x & 2) << 1) | ((x & 4) >> 1) | ((x & 8) >> 3);
}

__global__ __launch_bounds__(THREADS)
void routing_kernel(const float* __restrict__ caps, float* __restrict__ out) {
    __shared__ float  zbuf[4];
    __shared__ float2 part[4][32];

    const int tid = threadIdx.x;
    const int w   = tid >> 5;          // warp: owns rows 16w .. 16w+15
    const int l   = tid & 31;          // lane: owns cols 2l, 2l+1
    const int blk = blockIdx.x;

    // ---- Load tile directly into registers. Warp-instr = 256B contiguous, coalesced.
    float2 u[16];
    const float* base = caps + (size_t)blk * (NCAP * DDIM) + (w * 16) * DDIM + 2 * l;
    #pragma unroll
    for (int r = 0; r < 16; r++)
        u[r] = *reinterpret_cast<const float2*>(base + r * DDIM);

    float b_mine = 0.0f;   // routing logit for row r_mine = brev4(l&15) of this warp
    float v0, v1;          // v[2l], v[2l+1] (replicated across warps)

    // ================= iteration 0: b == 0 -> c uniform = 1/64 =================
    {
        float p0 = 0.f, p1 = 0.f;
        #pragma unroll
        for (int r = 0; r < 16; r++) { p0 += u[r].x; p1 += u[r].y; }
        p0 *= (1.0f / 64.0f);
        p1 *= (1.0f / 64.0f);
        part[w][l] = make_float2(p0, p1);
        __syncthreads();
        float s0 = 0.f, s1 = 0.f;
        #pragma unroll
        for (int ww = 0; ww < 4; ww++) {
            float2 q = part[ww][l];
            s0 += q.x; s1 += q.y;
        }
        float t = s0 * s0 + s1 * s1;
        #pragma unroll
        for (int o = 16; o; o >>= 1) t += __shfl_xor_sync(0xFFFFFFFFu, t, o);
        float scale = t / (1.0f + t) / (sqrtf(t) + EPS);
        v0 = scale * s0;
        v1 = scale * s1;
    }

    // ================= iterations 1, 2 =================
    #pragma unroll
    for (int it = 1; it < 3; it++) {
        // ---- agreement: b[n] += sum_d U[n][d] * v[d]
        // lane partial over its 2 columns, for this warp's 16 rows
        float p[16];
        #pragma unroll
        for (int r = 0; r < 16; r++)
            p[r] = fmaf(u[r].x, v0, u[r].y * v1);

        // halving butterfly: rounds m=1,2,4,8; after, lane holds the 16-lane-group
        // total for row r_mine = brev4(l&15); final xor-16 adds the two groups.
        #pragma unroll
        for (int round = 0; round < 4; round++) {
            const int m    = 1 << round;
            const int half = 8 >> round;   // 8,4,2,1
            const bool up  = (l & m) != 0;
            #pragma unroll
            for (int i = 0; i < 8; i++) {
                if (i < half) {
                    float a  = p[i];
                    float bb = p[i + half];
                    float send = up ? a : bb;
                    float keep = up ? bb : a;
                    p[i] = keep + __shfl_xor_sync(0xFFFFFFFFu, send, m);
                }
            }
        }
        b_mine += p[0] + __shfl_xor_sync(0xFFFFFFFFu, p[0], 16);

        // ---- softmax over all 64 rows (no max-subtraction: |b| <~ 25, exp safe)
        float e  = __expf(b_mine);
        float Zw = e;
        #pragma unroll
        for (int o = 8; o; o >>= 1)   // sum over the 16 distinct rows of this warp
            Zw += __shfl_xor_sync(0xFFFFFFFFu, Zw, o);
        if (l == 0) zbuf[w] = Zw;
        __syncthreads();
        float Z  = zbuf[0] + zbuf[1] + zbuf[2] + zbuf[3];
        float cm = e * (1.0f / Z);

        // ---- s-phase: s[d] = sum_n c[n] U[n][d]; c[r] via single shuffles
        float p0 = 0.f, p1 = 0.f;
        #pragma unroll
        for (int r = 0; r < 16; r++) {
            float cr = __shfl_sync(0xFFFFFFFFu, cm, brev4(r));
            p0 = fmaf(cr, u[r].x, p0);
            p1 = fmaf(cr, u[r].y, p1);
        }
        part[w][l] = make_float2(p0, p1);
        __syncthreads();
        float s0 = 0.f, s1 = 0.f;
        #pragma unroll
        for (int ww = 0; ww < 4; ww++) {
            float2 q = part[ww][l];
            s0 += q.x; s1 += q.y;
        }

        // ---- squash
        float t = s0 * s0 + s1 * s1;
        #pragma unroll
        for (int o = 16; o; o >>= 1) t += __shfl_xor_sync(0xFFFFFFFFu, t, o);
        float scale = t / (1.0f + t) / (sqrtf(t) + EPS);
        v0 = scale * s0;
        v1 = scale * s1;
    }

    // ---- store v (warp 0 only; 256B coalesced)
    if (w == 0) {
        float2* o2 = reinterpret_cast<float2*>(out + (size_t)blk * DDIM);
        o2[l] = make_float2(v0, v1);
    }
}

extern "C" void kernel_launch(void* const* d_in, const int* in_sizes, int n_in,
                              void* d_out, int out_size) {
    const float* caps = (const float*)d_in[0];
    float* out = (float*)d_out;
    int B = in_sizes[0] / (NCAP * DDIM);   // 16384
    routing_kernel<<<B, THREADS>>>(caps, out);
}